// round 16
// baseline (speedup 1.0000x reference)
#include <cuda_runtime.h>
#include <cuda_bf16.h>
#include <mma.h>
#include <math.h>
#include <stdint.h>

using namespace nvcuda;

// ---------------------------------------------------------------------------
// GCN_9062380994846: 3-layer GCN + mean pool + classifier + log_softmax
// GEMM1/2: WMMA bf16 hi/lo split (K'=768), single-wave (139 CTAs), fp32->bf16
// conversion fused into the GEMM A-prefetch (no convert_in kernel).
// Layer 3 collapsed: q = h2 @ (W3@Wc); wide per-graph gather; cls fused into
// pool via last-block. fill atomic-free via ordinal trick.
// ---------------------------------------------------------------------------

#define N_NODES   20000
#define N_EDGES   320000
#define DIM       256
#define N_GRAPHS  64
#define N_CLASSES 10
#define SCAN_BLK  256
#define N_SCANB   ((N_NODES + SCAN_BLK - 1) / SCAN_BLK)   // 79
#define PAD_M     20016                                    // 139 * 144
#define KP        768
#define NPOOL_BLK (N_GRAPHS * 16)                          // 1024

// ---------------- scratch ----------------------------------------------------
__device__ float g_T[PAD_M * DIM];
__device__ float g_A[PAD_M * DIM];
__device__ float g_B[PAD_M * DIM];
__device__ __nv_bfloat16 g_Bext[2 * KP * DIM];   // layers 1-2 only
__device__ float g_W3Wc[DIM * N_CLASSES];
__device__ float g_bWc[N_CLASSES];
__device__ float g_q[N_NODES * N_CLASSES];
__device__ int   g_src32[N_EDGES];
__device__ int   g_dst32[N_EDGES];
__device__ int   g_ord[N_EDGES];        // within-dst ordinal (from count atomic)
__device__ int   g_cnt[N_NODES];        // zero-init at load; restored by fill_kernel
__device__ int   g_off[N_NODES + 1];
__device__ int   g_csr[N_EDGES];
__device__ float g_w[N_EDGES];
__device__ float g_dinv[N_NODES];
__device__ int   g_bsum[N_SCANB];
__device__ int   g_gstart[N_GRAPHS + 1];
__device__ float g_pool[N_GRAPHS * N_CLASSES];
__device__ int   g_done;                // last-block counter (self-resetting)
__device__ int   g_ei_is64;
__device__ int   g_b_is64;

// ---------------- host-side aux ------------------------------------------------
static cudaStream_t g_side = nullptr;
static cudaEvent_t  g_evf = nullptr, g_evj = nullptr;
struct AuxInit {
    AuxInit() {
        cudaStreamCreateWithFlags(&g_side, cudaStreamNonBlocking);
        cudaEventCreateWithFlags(&g_evf, cudaEventDisableTiming);
        cudaEventCreateWithFlags(&g_evj, cudaEventDisableTiming);
    }
};
static AuxInit g_auxinit;

// ---------------- cp.async helpers ---------------------------------------------
__device__ __forceinline__ void cpa16(uint32_t dst, const void* src) {
    asm volatile("cp.async.cg.shared.global [%0], [%1], 16;" :: "r"(dst), "l"(src));
}
#define CP_COMMIT() asm volatile("cp.async.commit_group;" ::: "memory")
#define CP_WAIT(N)  asm volatile("cp.async.wait_group %0;" :: "n"(N) : "memory")

// ---------------- bf16 conversion helpers ----------------------------------------
__device__ __forceinline__ uint2 cvt_hi4(float4 v) {
    __nv_bfloat162 a = __floats2bfloat162_rn(v.x, v.y);
    __nv_bfloat162 b = __floats2bfloat162_rn(v.z, v.w);
    uint2 r;
    r.x = *reinterpret_cast<uint32_t*>(&a);
    r.y = *reinterpret_cast<uint32_t*>(&b);
    return r;
}
__device__ __forceinline__ uint2 cvt_lo4(float4 v) {
    __nv_bfloat162 a = __floats2bfloat162_rn(v.x, v.y);
    __nv_bfloat162 b = __floats2bfloat162_rn(v.z, v.w);
    float4 l = make_float4(v.x - __low2float(a), v.y - __high2float(a),
                           v.z - __low2float(b), v.w - __high2float(b));
    return cvt_hi4(l);
}

// ---------------- dtype detection + gstart seeding + pool zero -------------------
__global__ void detect_kernel(const void* ei, const void* batch) {
    int t = threadIdx.x;  // 1024 threads
    if (t == 0) { g_ei_is64 = 1; g_b_is64 = 1; }
    if (t <= N_GRAPHS) g_gstart[t] = N_NODES;
    if (t < N_GRAPHS * N_CLASSES) g_pool[t] = 0.0f;
    __syncthreads();
    long long v = ((const long long*)ei)[(long long)t * 312];
    if (v < 0 || v >= N_NODES) atomicExch(&g_ei_is64, 0);
    long long b = ((const long long*)batch)[t * 9];
    if (b < 0 || b >= N_GRAPHS) atomicExch(&g_b_is64, 0);
}

// ---------------- merged batch+edge conversion (g_cnt already zero) -------------
__global__ void convert_graph(const void* ei, const void* batch) {
    int i = blockIdx.x * blockDim.x + threadIdx.x;
    if (i < N_NODES) {
        int b = g_b_is64 ? (int)((const long long*)batch)[i] : ((const int*)batch)[i];
        b = min(max(b, 0), N_GRAPHS - 1);
        atomicMin(&g_gstart[b], i);
    }
    if (i >= N_EDGES) return;
    int s, d;
    if (g_ei_is64) {
        s = (int)((const long long*)ei)[i];
        d = (int)((const long long*)ei)[N_EDGES + i];
    } else {
        s = ((const int*)ei)[i];
        d = ((const int*)ei)[N_EDGES + i];
    }
    s = min(max(s, 0), N_NODES - 1);
    d = min(max(d, 0), N_NODES - 1);
    g_src32[i] = s;
    g_dst32[i] = d;
    g_ord[i] = atomicAdd(&g_cnt[d], 1);
}

// weights for layers 1-2: Bext = [hi(W); lo(W); hi(W)]
__global__ __launch_bounds__(256) void convert_w(const float* __restrict__ W1,
                                                 const float* __restrict__ W2) {
    int i = blockIdx.x * 256 + threadIdx.x;
    if (i >= 2 * DIM * DIM) return;
    int w = i >> 16, r = i & 0xFFFF;
    int k = r >> 8, n = r & 255;
    const float* W = (w == 0) ? W1 : W2;
    float v = W[k * DIM + n];
    __nv_bfloat16 h = __float2bfloat16(v);
    __nv_bfloat16 l = __float2bfloat16(v - __bfloat162float(h));
    __nv_bfloat16* Be = g_Bext + w * KP * DIM;
    Be[k * DIM + n] = h;
    Be[(256 + k) * DIM + n] = l;
    Be[(512 + k) * DIM + n] = h;
}

// W3Wc = W3 @ Wc (fp32 exact), bWc = b3 @ Wc + bc
__global__ __launch_bounds__(256) void w3wc_kernel(const float* __restrict__ W3,
                                                   const float* __restrict__ Wc,
                                                   const float* __restrict__ b3,
                                                   const float* __restrict__ bc) {
    int idx = blockIdx.x * 256 + threadIdx.x;
    if (idx < DIM * N_CLASSES) {
        int k = idx / N_CLASSES, c = idx % N_CLASSES;
        float s = 0.0f;
        for (int m = 0; m < DIM; m++) s += W3[k * DIM + m] * Wc[m * N_CLASSES + c];
        g_W3Wc[idx] = s;
    }
    if (idx < N_CLASSES) {
        float s = 0.0f;
        for (int k = 0; k < DIM; k++) s += b3[k] * Wc[k * N_CLASSES + idx];
        g_bWc[idx] = s + bc[idx];
    }
}

// ---------------- WMMA GEMM: C = [hi(A)|hi(A)|lo(A)] @ Bext ----------------------
// A read directly as fp32 (x or g_A), converted to bf16 in the prefetch path.
#define GBM 144
#define GBN 256
#define GBK 64
#define NCHUNK (KP / GBK)         // 12
#define A_LD  (GBK + 8)
#define B_LD  (GBN + 8)
#define A_SZ  (GBM * A_LD * 2)
#define B_SZ  (GBK * B_LD * 2)
#define GEMM_SMEM (2 * (A_SZ + B_SZ))
#define GEMM_THREADS 384

__global__ __launch_bounds__(GEMM_THREADS, 1) void gemm_wmma(
    const float* __restrict__ Asrc, int layer, float* __restrict__ C) {
    extern __shared__ __align__(16) char smem[];
    const int tid = threadIdx.x;
    const int wid = tid >> 5;
    const int wm = wid % 3;
    const int wn = wid / 3;
    const int rowBase = blockIdx.x * GBM;
    const __nv_bfloat16* Bext = g_Bext + layer * KP * DIM;

    __nv_bfloat16* As[2] = {(__nv_bfloat16*)smem, (__nv_bfloat16*)(smem + A_SZ)};
    __nv_bfloat16* Bs[2] = {(__nv_bfloat16*)(smem + 2 * A_SZ),
                            (__nv_bfloat16*)(smem + 2 * A_SZ + B_SZ)};

    // A tasks: 144 rows x 16 float4-segs = 2304, 6 per thread
    int arow[6], aseg[6];
#pragma unroll
    for (int t = 0; t < 6; t++) {
        int q = tid + t * GEMM_THREADS;
        arow[t] = q >> 4;
        aseg[t] = q & 15;
    }

    uint2 areg[6];
    auto loadA = [&](int c) {
        const int ko = (c & 3) * GBK;
        const bool lo = (c >= 8);
#pragma unroll
        for (int t = 0; t < 6; t++) {
            int gr = rowBase + arow[t];
            float4 v = make_float4(0.f, 0.f, 0.f, 0.f);
            if (gr < N_NODES)
                v = *reinterpret_cast<const float4*>(
                    &Asrc[gr * DIM + ko + aseg[t] * 4]);
            areg[t] = lo ? cvt_lo4(v) : cvt_hi4(v);
        }
    };
    auto stsA = [&](int s) {
#pragma unroll
        for (int t = 0; t < 6; t++)
            *reinterpret_cast<uint2*>(
                reinterpret_cast<char*>(As[s]) +
                (arow[t] * A_LD + aseg[t] * 4) * 2) = areg[t];
    };
    auto loadB = [&](int c) {
        const int s = c & 1;
        uint32_t bbase = (uint32_t)__cvta_generic_to_shared(Bs[s]);
        for (int q = tid; q < 2048; q += GEMM_THREADS) {
            int row = q >> 5, seg = q & 31;
            cpa16(bbase + (row * B_LD + seg * 8) * 2,
                  Bext + (c * GBK + row) * DIM + seg * 8);
        }
        CP_COMMIT();
    };

    wmma::fragment<wmma::accumulator, 16, 16, 16, float> acc[3][4];
#pragma unroll
    for (int i = 0; i < 3; i++)
#pragma unroll
        for (int j = 0; j < 4; j++) wmma::fill_fragment(acc[i][j], 0.0f);

    loadA(0);
    loadB(0);
    stsA(0);
    CP_WAIT(0);
    __syncthreads();

    for (int c = 0; c < NCHUNK; c++) {
        const int s = c & 1;
        if (c + 1 < NCHUNK) {
            loadA(c + 1);     // LDG issued early; consumed after compute
            loadB(c + 1);
        }
#pragma unroll
        for (int ks = 0; ks < GBK; ks += 16) {
            wmma::fragment<wmma::matrix_b, 16, 16, 16, __nv_bfloat16, wmma::row_major> bf[4];
#pragma unroll
            for (int j = 0; j < 4; j++)
                wmma::load_matrix_sync(bf[j], Bs[s] + ks * B_LD + wn * 64 + j * 16, B_LD);
#pragma unroll
            for (int i = 0; i < 3; i++) {
                wmma::fragment<wmma::matrix_a, 16, 16, 16, __nv_bfloat16, wmma::row_major> af;
                wmma::load_matrix_sync(af, As[s] + (wm * 48 + i * 16) * A_LD + ks, A_LD);
#pragma unroll
                for (int j = 0; j < 4; j++)
                    wmma::mma_sync(acc[i][j], af, bf[j], acc[i][j]);
            }
        }
        if (c + 1 < NCHUNK) {
            stsA(s ^ 1);
            CP_WAIT(0);
        }
        __syncthreads();
    }

#pragma unroll
    for (int i = 0; i < 3; i++)
#pragma unroll
        for (int j = 0; j < 4; j++)
            wmma::store_matrix_sync(
                &C[(rowBase + wm * 48 + i * 16) * DIM + wn * 64 + j * 16],
                acc[i][j], DIM, wmma::mem_row_major);
}

// ---------------- scan (mid folded into post) -------------------------------------
__global__ __launch_bounds__(SCAN_BLK) void scan_pre() {
    const int t = threadIdx.x;
    int i = blockIdx.x * SCAN_BLK + t;
    int v = (i < N_NODES) ? g_cnt[i] : 0;
#pragma unroll
    for (int o = 16; o; o >>= 1) v += __shfl_xor_sync(0xffffffffu, v, o);
    __shared__ int ws[8];
    if ((t & 31) == 0) ws[t >> 5] = v;
    __syncthreads();
    if (t < 8) {
        int s = ws[t];
#pragma unroll
        for (int o = 4; o; o >>= 1) s += __shfl_xor_sync(0xffu, s, o);
        if (t == 0) g_bsum[blockIdx.x] = s;
    }
}

__global__ __launch_bounds__(SCAN_BLK) void scan_post() {
    const int t = threadIdx.x;
    const int bid = blockIdx.x;
    __shared__ int ws[8];
    __shared__ int s_base;
    {
        int v = (t < N_SCANB && t < bid) ? g_bsum[t] : 0;
#pragma unroll
        for (int o = 16; o; o >>= 1) v += __shfl_xor_sync(0xffffffffu, v, o);
        if ((t & 31) == 0) ws[t >> 5] = v;
        __syncthreads();
        if (t < 8) {
            int s = ws[t];
#pragma unroll
            for (int o = 4; o; o >>= 1) s += __shfl_xor_sync(0xffu, s, o);
            if (t == 0) s_base = s;
        }
        __syncthreads();
    }
    if (bid == 0) {
        __shared__ int wt[8];
        int v = (t < N_SCANB) ? g_bsum[t] : 0;
#pragma unroll
        for (int o = 16; o; o >>= 1) v += __shfl_xor_sync(0xffffffffu, v, o);
        if ((t & 31) == 0) wt[t >> 5] = v;
        __syncthreads();
        if (t < 8) {
            int s = wt[t];
#pragma unroll
            for (int o = 4; o; o >>= 1) s += __shfl_xor_sync(0xffu, s, o);
            if (t == 0) g_off[N_NODES] = s;
        }
        if (t == 32) {
            g_gstart[N_GRAPHS] = N_NODES;
            for (int g = N_GRAPHS - 1; g >= 0; g--)
                g_gstart[g] = min(g_gstart[g], g_gstart[g + 1]);
        }
        __syncthreads();
    }
    int i = bid * SCAN_BLK + t;
    int c = (i < N_NODES) ? g_cnt[i] : 0;
    int v = c;
#pragma unroll
    for (int o = 1; o < 32; o <<= 1) {
        int u = __shfl_up_sync(0xffffffffu, v, o);
        if ((t & 31) >= o) v += u;
    }
    __shared__ int ws2[8];
    if ((t & 31) == 31) ws2[t >> 5] = v;
    __syncthreads();
    if (t < 8) {
        int s = ws2[t];
#pragma unroll
        for (int o = 1; o < 8; o <<= 1) {
            int u = __shfl_up_sync(0xffu, s, o);
            if (t >= o) s += u;
        }
        ws2[t] = s;
    }
    __syncthreads();
    int warpBase = (t >= 32) ? ws2[(t >> 5) - 1] : 0;
    int excl = s_base + warpBase + v - c;
    if (i < N_NODES) {
        g_off[i] = excl;
        g_dinv[i] = rsqrtf((float)c + 1.0f);
    }
}

// CSR fill — atomic-free via ordinal; restores g_cnt = 0
__global__ void fill_kernel() {
    int e = blockIdx.x * blockDim.x + threadIdx.x;
    if (e < N_NODES) g_cnt[e] = 0;
    if (e < N_EDGES) {
        int s = g_src32[e];
        int d = g_dst32[e];
        int p = g_off[d] + g_ord[e];
        g_csr[p] = s;
        g_w[p] = g_dinv[s] * g_dinv[d];
    }
}

// ---------------- aggregation ------------------------------------------------
// MODE 0: relu(agg + b) | MODE 1: relu(resid + agg + b)
template <int MODE>
__global__ __launch_bounds__(256) void agg_kernel(
    const float4* __restrict__ T4, const float4* __restrict__ bias4,
    const float4* __restrict__ resid4, float4* __restrict__ out4) {
    const int i = blockIdx.x;
    const int tid = threadIdx.x;
    const int d4 = tid & 63;
    const int eg = tid >> 6;
    const int e0 = g_off[i], e1 = g_off[i + 1];

    float4 a0 = make_float4(0.f, 0.f, 0.f, 0.f);
    float4 a1 = a0;
    int e = e0 + eg;
    for (; e + 4 < e1; e += 8) {
        int s0 = g_csr[e];
        float w0 = g_w[e];
        int s1 = g_csr[e + 4];
        float w1 = g_w[e + 4];
        float4 v0 = T4[s0 * 64 + d4];
        float4 v1 = T4[s1 * 64 + d4];
        a0.x = fmaf(w0, v0.x, a0.x); a0.y = fmaf(w0, v0.y, a0.y);
        a0.z = fmaf(w0, v0.z, a0.z); a0.w = fmaf(w0, v0.w, a0.w);
        a1.x = fmaf(w1, v1.x, a1.x); a1.y = fmaf(w1, v1.y, a1.y);
        a1.z = fmaf(w1, v1.z, a1.z); a1.w = fmaf(w1, v1.w, a1.w);
    }
    if (e < e1) {
        int s = g_csr[e];
        float w = g_w[e];
        float4 v = T4[s * 64 + d4];
        a0.x = fmaf(w, v.x, a0.x); a0.y = fmaf(w, v.y, a0.y);
        a0.z = fmaf(w, v.z, a0.z); a0.w = fmaf(w, v.w, a0.w);
    }
    a0.x += a1.x; a0.y += a1.y; a0.z += a1.z; a0.w += a1.w;

    __shared__ float4 part[3][64];
    if (eg > 0) part[eg - 1][d4] = a0;
    __syncthreads();
    if (eg == 0) {
        const float di = g_dinv[i];
        float4 self = T4[i * 64 + d4];
        float dii = di * di;
        float4 b = bias4[d4];
        float4 acc;
        acc.x = a0.x + part[0][d4].x + part[1][d4].x + part[2][d4].x + self.x * dii + b.x;
        acc.y = a0.y + part[0][d4].y + part[1][d4].y + part[2][d4].y + self.y * dii + b.y;
        acc.z = a0.z + part[0][d4].z + part[1][d4].z + part[2][d4].z + self.z * dii + b.z;
        acc.w = a0.w + part[0][d4].w + part[1][d4].w + part[2][d4].w + self.w * dii + b.w;
        if (MODE == 1) {
            float4 r = resid4[i * 64 + d4];
            acc.x += r.x; acc.y += r.y; acc.z += r.z; acc.w += r.w;
        }
        acc.x = fmaxf(acc.x, 0.f); acc.y = fmaxf(acc.y, 0.f);
        acc.z = fmaxf(acc.z, 0.f); acc.w = fmaxf(acc.w, 0.f);
        out4[i * 64 + d4] = acc;
    }
}

// ---------------- project_q: q[i][c] = h2[i] . W3Wc[:,c] -------------------------
__global__ __launch_bounds__(256) void project_q(const float* __restrict__ h) {
    const int tid = threadIdx.x;
    const int warp = tid >> 5, lane = tid & 31;
    float wreg[8][N_CLASSES];
#pragma unroll
    for (int j = 0; j < 8; j++)
#pragma unroll
        for (int c = 0; c < N_CLASSES; c++)
            wreg[j][c] = g_W3Wc[(lane + 32 * j) * N_CLASSES + c];

    const int base = blockIdx.x * 64;
#pragma unroll 1
    for (int it = 0; it < 8; it++) {
        int i = base + it * 8 + warp;
        if (i >= N_NODES) break;
        float hv[8];
#pragma unroll
        for (int j = 0; j < 8; j++) hv[j] = h[i * DIM + lane + 32 * j];
        float part[N_CLASSES];
#pragma unroll
        for (int c = 0; c < N_CLASSES; c++) {
            float s = 0.0f;
#pragma unroll
            for (int j = 0; j < 8; j++) s = fmaf(hv[j], wreg[j][c], s);
            part[c] = s;
        }
#pragma unroll
        for (int c = 0; c < N_CLASSES; c++)
#pragma unroll
            for (int o = 16; o; o >>= 1)
                part[c] += __shfl_xor_sync(0xffffffffu, part[c], o);
        if (lane < N_CLASSES) g_q[i * N_CLASSES + lane] = part[lane];
    }
}

// ---------------- pool (wide gather on q) + classifier (last block) --------------
__global__ __launch_bounds__(256) void pool_cls(float* __restrict__ out,
                                                int out_size) {
    const int g = blockIdx.x >> 4;
    const int slice = blockIdx.x & 15;
    const int tid = threadIdx.x;
    const int grp = tid / N_CLASSES;
    const int d = tid % N_CLASSES;
    const int r0 = g_gstart[g], r1 = g_gstart[g + 1];
    __shared__ float part[25][N_CLASSES];
    __shared__ int isLast;

    float acc = 0.0f;
    if (grp < 25) {
        for (int i = r0 + slice * 25 + grp; i < r1; i += 400) {
            float di = g_dinv[i];
            acc = fmaf(di * di, g_q[i * N_CLASSES + d], acc);
            const int e0 = g_off[i], e1 = g_off[i + 1];
#pragma unroll 2
            for (int e = e0; e < e1; e++)
                acc = fmaf(g_w[e], g_q[g_csr[e] * N_CLASSES + d], acc);
        }
        part[grp][d] = acc;
    }
    __syncthreads();
    if (tid < N_CLASSES) {
        float s = 0.0f;
#pragma unroll
        for (int k = 0; k < 25; k++) s += part[k][tid];
        atomicAdd(&g_pool[g * N_CLASSES + tid], s);
    }
    if (tid == 0) {
        __threadfence();
        int old = atomicAdd(&g_done, 1);
        isLast = (old == NPOOL_BLK - 1);
    }
    __syncthreads();
    if (isLast) {
        for (int idx = tid; idx < N_GRAPHS * N_CLASSES; idx += 256) {
            int gg = idx / N_CLASSES, c = idx % N_CLASSES;
            int n = g_gstart[gg + 1] - g_gstart[gg];
            float inv = 1.0f / fmaxf((float)n, 1.0f);
            float lg[N_CLASSES];
            float mx = -1e30f;
#pragma unroll
            for (int k = 0; k < N_CLASSES; k++) {
                lg[k] = g_pool[gg * N_CLASSES + k] * inv + g_bWc[k];
                mx = fmaxf(mx, lg[k]);
            }
            float sum = 0.0f;
#pragma unroll
            for (int k = 0; k < N_CLASSES; k++) sum += expf(lg[k] - mx);
            float lse = mx + logf(sum);
            out[idx] = lg[c];
            if (out_size >= 2 * N_GRAPHS * N_CLASSES)
                out[N_GRAPHS * N_CLASSES + idx] = lg[c] - lse;
        }
        __threadfence();
        if (tid == 0) g_done = 0;
    }
}

// ---------------- launch ----------------------------------------------------------
extern "C" void kernel_launch(void* const* d_in, const int* in_sizes, int n_in,
                              void* d_out, int out_size) {
    const float* x = (const float*)d_in[0];
    const void*  ei = d_in[1];
    const void*  batch = d_in[2];
    const float* W1 = (const float*)d_in[3];
    const float* b1 = (const float*)d_in[4];
    const float* W2 = (const float*)d_in[5];
    const float* b2 = (const float*)d_in[6];
    const float* W3 = (const float*)d_in[7];
    const float* b3 = (const float*)d_in[8];
    const float* Wc = (const float*)d_in[9];
    const float* bc = (const float*)d_in[10];
    float* out = (float*)d_out;

    float* T; float* A; float* B;
    cudaGetSymbolAddress((void**)&T, g_T);
    cudaGetSymbolAddress((void**)&A, g_A);
    cudaGetSymbolAddress((void**)&B, g_B);

    static int smem_set = 0;
    if (!smem_set) {
        cudaFuncSetAttribute(gemm_wmma, cudaFuncAttributeMaxDynamicSharedMemorySize,
                             GEMM_SMEM);
        smem_set = 1;
    }

    const int EDGE_GRID = (N_EDGES + 255) / 256;
    const int ggrid = PAD_M / GBM;  // 139

    const bool use_side = (g_side && g_evf && g_evj);

    if (use_side) {
        cudaEventRecord(g_evf, 0);
        cudaStreamWaitEvent(g_side, g_evf, 0);
        // side: graph preprocessing + W3Wc
        detect_kernel<<<1, 1024, 0, g_side>>>(ei, batch);
        convert_graph<<<EDGE_GRID, 256, 0, g_side>>>(ei, batch);
        scan_pre<<<N_SCANB, SCAN_BLK, 0, g_side>>>();
        scan_post<<<N_SCANB, SCAN_BLK, 0, g_side>>>();
        fill_kernel<<<EDGE_GRID, 256, 0, g_side>>>();
        w3wc_kernel<<<10, 256, 0, g_side>>>(W3, Wc, b3, bc);
        cudaEventRecord(g_evj, g_side);
        // main: convert_w + layer-1 GEMM (fp32 x converted on the fly)
        convert_w<<<(2 * DIM * DIM + 255) / 256, 256>>>(W1, W2);
        gemm_wmma<<<ggrid, GEMM_THREADS, GEMM_SMEM>>>(x, 0, T);
        cudaStreamWaitEvent(0, g_evj, 0);   // join before agg1
    } else {
        detect_kernel<<<1, 1024>>>(ei, batch);
        convert_graph<<<EDGE_GRID, 256>>>(ei, batch);
        scan_pre<<<N_SCANB, SCAN_BLK>>>();
        scan_post<<<N_SCANB, SCAN_BLK>>>();
        fill_kernel<<<EDGE_GRID, 256>>>();
        w3wc_kernel<<<10, 256>>>(W3, Wc, b3, bc);
        convert_w<<<(2 * DIM * DIM + 255) / 256, 256>>>(W1, W2);
        gemm_wmma<<<ggrid, GEMM_THREADS, GEMM_SMEM>>>(x, 0, T);
    }

    // layer 1 aggregate (fp32 only)
    agg_kernel<0><<<N_NODES, 256>>>((const float4*)T, (const float4*)b1, nullptr,
                                    (float4*)A);
    // layer 2 GEMM reads fp32 g_A directly (on-the-fly conversion)
    gemm_wmma<<<ggrid, GEMM_THREADS, GEMM_SMEM>>>(A, 1, T);
    agg_kernel<1><<<N_NODES, 256>>>((const float4*)T, (const float4*)b2,
                                    (const float4*)A, (float4*)B);
    // collapsed layer 3: project to 10 dims, per-graph gather + cls (last block)
    project_q<<<(N_NODES + 63) / 64, 256>>>(B);
    pool_cls<<<NPOOL_BLK, 256>>>(out, out_size);
}

// round 17
// speedup vs baseline: 1.1671x; 1.1671x over previous
#include <cuda_runtime.h>
#include <cuda_bf16.h>
#include <mma.h>
#include <math.h>
#include <stdint.h>

using namespace nvcuda;

// ---------------------------------------------------------------------------
// GCN_9062380994846: 3-layer GCN + mean pool + classifier + log_softmax
// GEMM1/2: WMMA bf16 hi/lo split (K'=768), single-wave grid (139 CTAs).
// Layer 3 collapsed: q = h2 @ (W3@Wc), wide per-graph gather on q, tiny cls.
// fill atomic-free via ordinal trick. w3wc merged into convert_w.
// ---------------------------------------------------------------------------

#define N_NODES   20000
#define N_EDGES   320000
#define DIM       256
#define N_GRAPHS  64
#define N_CLASSES 10
#define SCAN_BLK  256
#define N_SCANB   ((N_NODES + SCAN_BLK - 1) / SCAN_BLK)   // 79
#define PAD_M     20016                                    // 139 * 144
#define KP        768

// ---------------- scratch ----------------------------------------------------
__device__ float g_T[PAD_M * DIM];
__device__ float g_A[PAD_M * DIM];
__device__ float g_B[PAD_M * DIM];
__device__ __nv_bfloat16 g_Ahi[PAD_M * DIM];
__device__ __nv_bfloat16 g_Alo[PAD_M * DIM];
__device__ __nv_bfloat16 g_Bext[2 * KP * DIM];   // layers 1-2 only
__device__ float g_W3Wc[DIM * N_CLASSES];
__device__ float g_bWc[N_CLASSES];
__device__ float g_q[N_NODES * N_CLASSES];
__device__ int   g_src32[N_EDGES];
__device__ int   g_dst32[N_EDGES];
__device__ int   g_ord[N_EDGES];        // within-dst ordinal (from count atomic)
__device__ int   g_cnt[N_NODES];        // zero-init at load; restored by fill_kernel
__device__ int   g_off[N_NODES + 1];
__device__ int   g_csr[N_EDGES];
__device__ float g_w[N_EDGES];
__device__ float g_dinv[N_NODES];
__device__ int   g_bsum[N_SCANB];
__device__ int   g_gstart[N_GRAPHS + 1];
__device__ float g_pool[N_GRAPHS * N_CLASSES];
__device__ int   g_ei_is64;
__device__ int   g_b_is64;

// ---------------- host-side aux (created at static init, reused forever) ------
static cudaStream_t g_side = nullptr;
static cudaEvent_t  g_evf = nullptr, g_evj = nullptr, g_evw = nullptr;
struct AuxInit {
    AuxInit() {
        cudaStreamCreateWithFlags(&g_side, cudaStreamNonBlocking);
        cudaEventCreateWithFlags(&g_evf, cudaEventDisableTiming);
        cudaEventCreateWithFlags(&g_evj, cudaEventDisableTiming);
        cudaEventCreateWithFlags(&g_evw, cudaEventDisableTiming);
    }
};
static AuxInit g_auxinit;

// ---------------- cp.async helpers ---------------------------------------------
__device__ __forceinline__ void cpa16(uint32_t dst, const void* src) {
    asm volatile("cp.async.cg.shared.global [%0], [%1], 16;" :: "r"(dst), "l"(src));
}
#define CP_COMMIT() asm volatile("cp.async.commit_group;" ::: "memory")
#define CP_WAIT(N)  asm volatile("cp.async.wait_group %0;" :: "n"(N) : "memory")

// ---------------- dtype detection + gstart seeding + pool zero -------------------
__global__ void detect_kernel(const void* ei, const void* batch) {
    int t = threadIdx.x;  // 1024 threads
    if (t == 0) { g_ei_is64 = 1; g_b_is64 = 1; }
    if (t <= N_GRAPHS) g_gstart[t] = N_NODES;
    if (t < N_GRAPHS * N_CLASSES) g_pool[t] = 0.0f;
    __syncthreads();
    long long v = ((const long long*)ei)[(long long)t * 312];
    if (v < 0 || v >= N_NODES) atomicExch(&g_ei_is64, 0);
    long long b = ((const long long*)batch)[t * 9];
    if (b < 0 || b >= N_GRAPHS) atomicExch(&g_b_is64, 0);
}

// ---------------- merged batch+edge conversion (g_cnt already zero) -------------
// Degree count atomic's return value = within-node ordinal -> atomic-free fill.
__global__ void convert_graph(const void* ei, const void* batch) {
    int i = blockIdx.x * blockDim.x + threadIdx.x;
    if (i < N_NODES) {
        int b = g_b_is64 ? (int)((const long long*)batch)[i] : ((const int*)batch)[i];
        b = min(max(b, 0), N_GRAPHS - 1);
        atomicMin(&g_gstart[b], i);
    }
    if (i >= N_EDGES) return;
    int s, d;
    if (g_ei_is64) {
        s = (int)((const long long*)ei)[i];
        d = (int)((const long long*)ei)[N_EDGES + i];
    } else {
        s = ((const int*)ei)[i];
        d = ((const int*)ei)[N_EDGES + i];
    }
    s = min(max(s, 0), N_NODES - 1);
    d = min(max(d, 0), N_NODES - 1);
    g_src32[i] = s;
    g_dst32[i] = d;
    g_ord[i] = atomicAdd(&g_cnt[d], 1);
}

// ---------------- fp32 -> bf16 hi/lo ---------------------------------------------
__global__ __launch_bounds__(256) void convert_in(const float4* __restrict__ src) {
    int i = blockIdx.x * 256 + threadIdx.x;
    if (i >= PAD_M * 64) return;
    int row = i >> 6;
    float4 v = make_float4(0.f, 0.f, 0.f, 0.f);
    if (row < N_NODES) v = src[i];
    __nv_bfloat162 h0 = __floats2bfloat162_rn(v.x, v.y);
    __nv_bfloat162 h1 = __floats2bfloat162_rn(v.z, v.w);
    float l0 = v.x - __low2float(h0);
    float l1 = v.y - __high2float(h0);
    float l2 = v.z - __low2float(h1);
    float l3 = v.w - __high2float(h1);
    ((__nv_bfloat162*)g_Ahi)[2 * i]     = h0;
    ((__nv_bfloat162*)g_Ahi)[2 * i + 1] = h1;
    ((__nv_bfloat162*)g_Alo)[2 * i]     = __floats2bfloat162_rn(l0, l1);
    ((__nv_bfloat162*)g_Alo)[2 * i + 1] = __floats2bfloat162_rn(l2, l3);
}

// convert_w + w3wc merged: blocks [0,512) convert W1/W2 to bf16 hi/lo;
// blocks [512,523) compute W3Wc = W3 @ Wc and bWc = b3 @ Wc + bc.
#define CW_BLOCKS (512 + (DIM * N_CLASSES + N_CLASSES + 255) / 256)   // 523
__global__ __launch_bounds__(256) void convert_w(const float* __restrict__ W1,
                                                 const float* __restrict__ W2,
                                                 const float* __restrict__ W3,
                                                 const float* __restrict__ Wc,
                                                 const float* __restrict__ b3,
                                                 const float* __restrict__ bc) {
    int i = blockIdx.x * 256 + threadIdx.x;
    if (i < 2 * DIM * DIM) {
        int w = i >> 16, r = i & 0xFFFF;
        int k = r >> 8, n = r & 255;
        const float* W = (w == 0) ? W1 : W2;
        float v = W[k * DIM + n];
        __nv_bfloat16 h = __float2bfloat16(v);
        __nv_bfloat16 l = __float2bfloat16(v - __bfloat162float(h));
        __nv_bfloat16* Be = g_Bext + w * KP * DIM;
        Be[k * DIM + n] = h;
        Be[(256 + k) * DIM + n] = l;
        Be[(512 + k) * DIM + n] = h;
        return;
    }
    int idx = i - 2 * DIM * DIM;
    if (idx < DIM * N_CLASSES) {
        int k = idx / N_CLASSES, c = idx % N_CLASSES;
        float s = 0.0f;
        for (int m = 0; m < DIM; m++) s += W3[k * DIM + m] * Wc[m * N_CLASSES + c];
        g_W3Wc[idx] = s;
    } else if (idx < DIM * N_CLASSES + N_CLASSES) {
        int c = idx - DIM * N_CLASSES;
        float s = 0.0f;
        for (int k = 0; k < DIM; k++) s += b3[k] * Wc[k * N_CLASSES + c];
        g_bWc[c] = s + bc[c];
    }
}

// ---------------- WMMA GEMM: C[PAD_M,256] = [Ahi|Ahi|Alo] @ Bext ----------------
#define GBM 144
#define GBN 256
#define GBK 64
#define NCHUNK (KP / GBK)         // 12
#define A_LD  (GBK + 8)
#define B_LD  (GBN + 8)
#define A_SZ  (GBM * A_LD * 2)
#define B_SZ  (GBK * B_LD * 2)
#define GEMM_SMEM (2 * (A_SZ + B_SZ))
#define GEMM_THREADS 384

__global__ __launch_bounds__(GEMM_THREADS, 1) void gemm_wmma(int layer,
                                                             float* __restrict__ C) {
    extern __shared__ __align__(16) char smem[];
    const int tid = threadIdx.x;
    const int wid = tid >> 5;
    const int wm = wid % 3;
    const int wn = wid / 3;
    const int rowBase = blockIdx.x * GBM;
    const __nv_bfloat16* Bext = g_Bext + layer * KP * DIM;

    __nv_bfloat16* As[2] = {(__nv_bfloat16*)smem, (__nv_bfloat16*)(smem + A_SZ)};
    __nv_bfloat16* Bs[2] = {(__nv_bfloat16*)(smem + 2 * A_SZ),
                            (__nv_bfloat16*)(smem + 2 * A_SZ + B_SZ)};

    auto prefetch = [&](int c) {
        const int s = c & 1;
        const __nv_bfloat16* Ap = (c < 8) ? g_Ahi : g_Alo;
        const int ko = (c & 3) * GBK;
        uint32_t abase = (uint32_t)__cvta_generic_to_shared(As[s]);
#pragma unroll
        for (int t = 0; t < 3; t++) {
            int q = tid + t * GEMM_THREADS;
            int row = q >> 3, seg = q & 7;
            cpa16(abase + (row * A_LD + seg * 8) * 2,
                  Ap + (rowBase + row) * DIM + ko + seg * 8);
        }
        uint32_t bbase = (uint32_t)__cvta_generic_to_shared(Bs[s]);
        for (int q = tid; q < 2048; q += GEMM_THREADS) {
            int row = q >> 5, seg = q & 31;
            cpa16(bbase + (row * B_LD + seg * 8) * 2,
                  Bext + (c * GBK + row) * DIM + seg * 8);
        }
        CP_COMMIT();
    };

    wmma::fragment<wmma::accumulator, 16, 16, 16, float> acc[3][4];
#pragma unroll
    for (int i = 0; i < 3; i++)
#pragma unroll
        for (int j = 0; j < 4; j++) wmma::fill_fragment(acc[i][j], 0.0f);

    prefetch(0);

    for (int c = 0; c < NCHUNK; c++) {
        const int s = c & 1;
        if (c + 1 < NCHUNK) {
            prefetch(c + 1);
            CP_WAIT(1);
        } else {
            CP_WAIT(0);
        }
        __syncthreads();
#pragma unroll
        for (int ks = 0; ks < GBK; ks += 16) {
            wmma::fragment<wmma::matrix_b, 16, 16, 16, __nv_bfloat16, wmma::row_major> bf[4];
#pragma unroll
            for (int j = 0; j < 4; j++)
                wmma::load_matrix_sync(bf[j], Bs[s] + ks * B_LD + wn * 64 + j * 16, B_LD);
#pragma unroll
            for (int i = 0; i < 3; i++) {
                wmma::fragment<wmma::matrix_a, 16, 16, 16, __nv_bfloat16, wmma::row_major> af;
                wmma::load_matrix_sync(af, As[s] + (wm * 48 + i * 16) * A_LD + ks, A_LD);
#pragma unroll
                for (int j = 0; j < 4; j++)
                    wmma::mma_sync(acc[i][j], af, bf[j], acc[i][j]);
            }
        }
        __syncthreads();
    }

#pragma unroll
    for (int i = 0; i < 3; i++)
#pragma unroll
        for (int j = 0; j < 4; j++)
            wmma::store_matrix_sync(
                &C[(rowBase + wm * 48 + i * 16) * DIM + wn * 64 + j * 16],
                acc[i][j], DIM, wmma::mem_row_major);
}

// ---------------- scan (mid folded into post) -------------------------------------
__global__ __launch_bounds__(SCAN_BLK) void scan_pre() {
    const int t = threadIdx.x;
    int i = blockIdx.x * SCAN_BLK + t;
    int v = (i < N_NODES) ? g_cnt[i] : 0;
#pragma unroll
    for (int o = 16; o; o >>= 1) v += __shfl_xor_sync(0xffffffffu, v, o);
    __shared__ int ws[8];
    if ((t & 31) == 0) ws[t >> 5] = v;
    __syncthreads();
    if (t < 8) {
        int s = ws[t];
#pragma unroll
        for (int o = 4; o; o >>= 1) s += __shfl_xor_sync(0xffu, s, o);
        if (t == 0) g_bsum[blockIdx.x] = s;
    }
}

__global__ __launch_bounds__(SCAN_BLK) void scan_post() {
    const int t = threadIdx.x;
    const int bid = blockIdx.x;
    __shared__ int ws[8];
    __shared__ int s_base;
    {
        int v = (t < N_SCANB && t < bid) ? g_bsum[t] : 0;
#pragma unroll
        for (int o = 16; o; o >>= 1) v += __shfl_xor_sync(0xffffffffu, v, o);
        if ((t & 31) == 0) ws[t >> 5] = v;
        __syncthreads();
        if (t < 8) {
            int s = ws[t];
#pragma unroll
            for (int o = 4; o; o >>= 1) s += __shfl_xor_sync(0xffu, s, o);
            if (t == 0) s_base = s;
        }
        __syncthreads();
    }
    if (bid == 0) {
        __shared__ int wt[8];
        int v = (t < N_SCANB) ? g_bsum[t] : 0;
#pragma unroll
        for (int o = 16; o; o >>= 1) v += __shfl_xor_sync(0xffffffffu, v, o);
        if ((t & 31) == 0) wt[t >> 5] = v;
        __syncthreads();
        if (t < 8) {
            int s = wt[t];
#pragma unroll
            for (int o = 4; o; o >>= 1) s += __shfl_xor_sync(0xffu, s, o);
            if (t == 0) g_off[N_NODES] = s;
        }
        if (t == 32) {  // serial suffix-min for empty graphs, separate warp
            g_gstart[N_GRAPHS] = N_NODES;
            for (int g = N_GRAPHS - 1; g >= 0; g--)
                g_gstart[g] = min(g_gstart[g], g_gstart[g + 1]);
        }
        __syncthreads();
    }
    int i = bid * SCAN_BLK + t;
    int c = (i < N_NODES) ? g_cnt[i] : 0;
    int v = c;
#pragma unroll
    for (int o = 1; o < 32; o <<= 1) {
        int u = __shfl_up_sync(0xffffffffu, v, o);
        if ((t & 31) >= o) v += u;
    }
    __shared__ int ws2[8];
    if ((t & 31) == 31) ws2[t >> 5] = v;
    __syncthreads();
    if (t < 8) {
        int s = ws2[t];
#pragma unroll
        for (int o = 1; o < 8; o <<= 1) {
            int u = __shfl_up_sync(0xffu, s, o);
            if (t >= o) s += u;
        }
        ws2[t] = s;
    }
    __syncthreads();
    int warpBase = (t >= 32) ? ws2[(t >> 5) - 1] : 0;
    int excl = s_base + warpBase + v - c;
    if (i < N_NODES) {
        g_off[i] = excl;
        g_dinv[i] = rsqrtf((float)c + 1.0f);
    }
}

// CSR fill — atomic-free via ordinal; restores g_cnt = 0 for the next call
__global__ void fill_kernel() {
    int e = blockIdx.x * blockDim.x + threadIdx.x;
    if (e < N_NODES) g_cnt[e] = 0;   // scan_post was the last reader
    if (e < N_EDGES) {
        int s = g_src32[e];
        int d = g_dst32[e];
        int p = g_off[d] + g_ord[e];
        g_csr[p] = s;
        g_w[p] = g_dinv[s] * g_dinv[d];
    }
}

// ---------------- aggregation (+ fused bf16 hi/lo output for next GEMM) ---------
template <int MODE, int WRITE_BF>
__global__ __launch_bounds__(256) void agg_kernel(
    const float4* __restrict__ T4, const float4* __restrict__ bias4,
    const float4* __restrict__ resid4, float4* __restrict__ out4) {
    const int i = blockIdx.x;
    const int tid = threadIdx.x;
    const int d4 = tid & 63;
    const int eg = tid >> 6;
    const int e0 = g_off[i], e1 = g_off[i + 1];

    float4 a0 = make_float4(0.f, 0.f, 0.f, 0.f);
    float4 a1 = a0;
    int e = e0 + eg;
    for (; e + 4 < e1; e += 8) {
        int s0 = g_csr[e];
        float w0 = g_w[e];
        int s1 = g_csr[e + 4];
        float w1 = g_w[e + 4];
        float4 v0 = T4[s0 * 64 + d4];
        float4 v1 = T4[s1 * 64 + d4];
        a0.x = fmaf(w0, v0.x, a0.x); a0.y = fmaf(w0, v0.y, a0.y);
        a0.z = fmaf(w0, v0.z, a0.z); a0.w = fmaf(w0, v0.w, a0.w);
        a1.x = fmaf(w1, v1.x, a1.x); a1.y = fmaf(w1, v1.y, a1.y);
        a1.z = fmaf(w1, v1.z, a1.z); a1.w = fmaf(w1, v1.w, a1.w);
    }
    if (e < e1) {
        int s = g_csr[e];
        float w = g_w[e];
        float4 v = T4[s * 64 + d4];
        a0.x = fmaf(w, v.x, a0.x); a0.y = fmaf(w, v.y, a0.y);
        a0.z = fmaf(w, v.z, a0.z); a0.w = fmaf(w, v.w, a0.w);
    }
    a0.x += a1.x; a0.y += a1.y; a0.z += a1.z; a0.w += a1.w;

    __shared__ float4 part[3][64];
    if (eg > 0) part[eg - 1][d4] = a0;
    __syncthreads();
    if (eg == 0) {
        const float di = g_dinv[i];
        float4 self = T4[i * 64 + d4];
        float dii = di * di;
        float4 b = bias4[d4];
        float4 acc;
        acc.x = a0.x + part[0][d4].x + part[1][d4].x + part[2][d4].x + self.x * dii + b.x;
        acc.y = a0.y + part[0][d4].y + part[1][d4].y + part[2][d4].y + self.y * dii + b.y;
        acc.z = a0.z + part[0][d4].z + part[1][d4].z + part[2][d4].z + self.z * dii + b.z;
        acc.w = a0.w + part[0][d4].w + part[1][d4].w + part[2][d4].w + self.w * dii + b.w;
        if (MODE == 1) {
            float4 r = resid4[i * 64 + d4];
            acc.x += r.x; acc.y += r.y; acc.z += r.z; acc.w += r.w;
        }
        if (MODE <= 1) {
            acc.x = fmaxf(acc.x, 0.f); acc.y = fmaxf(acc.y, 0.f);
            acc.z = fmaxf(acc.z, 0.f); acc.w = fmaxf(acc.w, 0.f);
        }
        out4[i * 64 + d4] = acc;
        if (WRITE_BF) {
            __nv_bfloat162 h0 = __floats2bfloat162_rn(acc.x, acc.y);
            __nv_bfloat162 h1 = __floats2bfloat162_rn(acc.z, acc.w);
            float l0 = acc.x - __low2float(h0);
            float l1 = acc.y - __high2float(h0);
            float l2 = acc.z - __low2float(h1);
            float l3 = acc.w - __high2float(h1);
            int base = i * 128 + d4 * 2;
            ((__nv_bfloat162*)g_Ahi)[base]     = h0;
            ((__nv_bfloat162*)g_Ahi)[base + 1] = h1;
            ((__nv_bfloat162*)g_Alo)[base]     = __floats2bfloat162_rn(l0, l1);
            ((__nv_bfloat162*)g_Alo)[base + 1] = __floats2bfloat162_rn(l2, l3);
        }
    }
}

// ---------------- project_q: q[i][c] = h2[i] . W3Wc[:,c]  (20000 x 10) ----------
__global__ __launch_bounds__(256) void project_q(const float* __restrict__ h) {
    const int tid = threadIdx.x;
    const int warp = tid >> 5, lane = tid & 31;
    float wreg[8][N_CLASSES];
#pragma unroll
    for (int j = 0; j < 8; j++)
#pragma unroll
        for (int c = 0; c < N_CLASSES; c++)
            wreg[j][c] = g_W3Wc[(lane + 32 * j) * N_CLASSES + c];

    const int base = blockIdx.x * 64;
#pragma unroll 1
    for (int it = 0; it < 8; it++) {
        int i = base + it * 8 + warp;
        if (i >= N_NODES) break;
        float hv[8];
#pragma unroll
        for (int j = 0; j < 8; j++) hv[j] = h[i * DIM + lane + 32 * j];
        float part[N_CLASSES];
#pragma unroll
        for (int c = 0; c < N_CLASSES; c++) {
            float s = 0.0f;
#pragma unroll
            for (int j = 0; j < 8; j++) s = fmaf(hv[j], wreg[j][c], s);
            part[c] = s;
        }
#pragma unroll
        for (int c = 0; c < N_CLASSES; c++)
#pragma unroll
            for (int o = 16; o; o >>= 1)
                part[c] += __shfl_xor_sync(0xffffffffu, part[c], o);
        if (lane < N_CLASSES) g_q[i * N_CLASSES + lane] = part[lane];
    }
}

// ---------------- pool_accum: wide per-graph gather on q -------------------------
__global__ __launch_bounds__(256) void pool_accum() {
    const int g = blockIdx.x >> 4;
    const int slice = blockIdx.x & 15;
    const int tid = threadIdx.x;
    const int grp = tid / N_CLASSES;     // 0..24 active (tid<250)
    const int d = tid % N_CLASSES;
    const int r0 = g_gstart[g], r1 = g_gstart[g + 1];
    __shared__ float part[25][N_CLASSES];

    float acc = 0.0f;
    if (grp < 25) {
        for (int i = r0 + slice * 25 + grp; i < r1; i += 400) {
            float di = g_dinv[i];
            acc = fmaf(di * di, g_q[i * N_CLASSES + d], acc);
            const int e0 = g_off[i], e1 = g_off[i + 1];
#pragma unroll 2
            for (int e = e0; e < e1; e++)
                acc = fmaf(g_w[e], g_q[g_csr[e] * N_CLASSES + d], acc);
        }
        part[grp][d] = acc;
    }
    __syncthreads();
    if (tid < N_CLASSES) {
        float s = 0.0f;
#pragma unroll
        for (int k = 0; k < 25; k++) s += part[k][tid];
        atomicAdd(&g_pool[g * N_CLASSES + tid], s);
    }
}

// ---------------- classifier: logits = pool/n + bWc; log_softmax -----------------
__global__ __launch_bounds__(32) void cls_kernel(float* __restrict__ out,
                                                 int out_size) {
    const int g = blockIdx.x;
    const int t = threadIdx.x;
    __shared__ float logits[N_CLASSES];
    int n = g_gstart[g + 1] - g_gstart[g];
    float inv = 1.0f / fmaxf((float)n, 1.0f);
    if (t < N_CLASSES)
        logits[t] = g_pool[g * N_CLASSES + t] * inv + g_bWc[t];
    __syncwarp();
    if (t < N_CLASSES) {
        float mx = -1e30f;
#pragma unroll
        for (int k = 0; k < N_CLASSES; k++) mx = fmaxf(mx, logits[k]);
        float sum = 0.0f;
#pragma unroll
        for (int k = 0; k < N_CLASSES; k++) sum += expf(logits[k] - mx);
        float lse = mx + logf(sum);
        out[g * N_CLASSES + t] = logits[t];
        if (out_size >= 2 * N_GRAPHS * N_CLASSES)
            out[N_GRAPHS * N_CLASSES + g * N_CLASSES + t] = logits[t] - lse;
    }
}

// ---------------- launch ----------------------------------------------------------
extern "C" void kernel_launch(void* const* d_in, const int* in_sizes, int n_in,
                              void* d_out, int out_size) {
    const float* x = (const float*)d_in[0];
    const void*  ei = d_in[1];
    const void*  batch = d_in[2];
    const float* W1 = (const float*)d_in[3];
    const float* b1 = (const float*)d_in[4];
    const float* W2 = (const float*)d_in[5];
    const float* b2 = (const float*)d_in[6];
    const float* W3 = (const float*)d_in[7];
    const float* b3 = (const float*)d_in[8];
    const float* Wc = (const float*)d_in[9];
    const float* bc = (const float*)d_in[10];
    float* out = (float*)d_out;

    float* T; float* A; float* B;
    cudaGetSymbolAddress((void**)&T, g_T);
    cudaGetSymbolAddress((void**)&A, g_A);
    cudaGetSymbolAddress((void**)&B, g_B);

    static int smem_set = 0;
    if (!smem_set) {
        cudaFuncSetAttribute(gemm_wmma, cudaFuncAttributeMaxDynamicSharedMemorySize,
                             GEMM_SMEM);
        smem_set = 1;
    }

    const int CONV_GRID = (PAD_M * 64 + 255) / 256;
    const int EDGE_GRID = (N_EDGES + 255) / 256;
    const int ggrid = PAD_M / GBM;  // 139

    const bool use_side = (g_side && g_evf && g_evj && g_evw);

    if (use_side) {
        cudaEventRecord(g_evf, 0);
        cudaStreamWaitEvent(g_side, g_evf, 0);
        // side #0: convert_w + w3wc merged (gemm1 dependency, event-gated)
        convert_w<<<CW_BLOCKS, 256, 0, g_side>>>(W1, W2, W3, Wc, b3, bc);
        cudaEventRecord(g_evw, g_side);
        // main: convert_in (overlaps convert_w)
        convert_in<<<CONV_GRID, 256>>>((const float4*)x);
        // side: detect + graph conversion + scans + fill
        detect_kernel<<<1, 1024, 0, g_side>>>(ei, batch);
        convert_graph<<<EDGE_GRID, 256, 0, g_side>>>(ei, batch);
        scan_pre<<<N_SCANB, SCAN_BLK, 0, g_side>>>();
        // main: layer-1 GEMM
        cudaStreamWaitEvent(0, g_evw, 0);
        gemm_wmma<<<ggrid, GEMM_THREADS, GEMM_SMEM>>>(0, T);
        scan_post<<<N_SCANB, SCAN_BLK, 0, g_side>>>();
        fill_kernel<<<EDGE_GRID, 256, 0, g_side>>>();
        cudaEventRecord(g_evj, g_side);
        cudaStreamWaitEvent(0, g_evj, 0);   // join before agg1
    } else {
        convert_w<<<CW_BLOCKS, 256>>>(W1, W2, W3, Wc, b3, bc);
        convert_in<<<CONV_GRID, 256>>>((const float4*)x);
        detect_kernel<<<1, 1024>>>(ei, batch);
        convert_graph<<<EDGE_GRID, 256>>>(ei, batch);
        scan_pre<<<N_SCANB, SCAN_BLK>>>();
        gemm_wmma<<<ggrid, GEMM_THREADS, GEMM_SMEM>>>(0, T);
        scan_post<<<N_SCANB, SCAN_BLK>>>();
        fill_kernel<<<EDGE_GRID, 256>>>();
    }

    // layer 1 aggregate (writes bf16 hi/lo for layer-2 GEMM)
    agg_kernel<0, 1><<<N_NODES, 256>>>((const float4*)T, (const float4*)b1, nullptr,
                                       (float4*)A);
    // layer 2 (h2 fp32 only — layer 3 consumed algebraically)
    gemm_wmma<<<ggrid, GEMM_THREADS, GEMM_SMEM>>>(1, T);
    agg_kernel<1, 0><<<N_NODES, 256>>>((const float4*)T, (const float4*)b2,
                                       (const float4*)A, (float4*)B);
    // collapsed layer 3: project to 10 dims, wide per-graph gather, classifier
    project_q<<<(N_NODES + 63) / 64, 256>>>(B);
    pool_accum<<<N_GRAPHS * 16, 256>>>();
    cls_kernel<<<N_GRAPHS, 32>>>(out, out_size);
}